// round 6
// baseline (speedup 1.0000x reference)
#include <cuda_runtime.h>

// ---------------------------------------------------------------------------
// TinyMixedHeteroLinkPredictor — round 6: fused, shared-LUT, occupancy-tuned.
//
//   logit(e) = feat[tab_s(t)][src] . v_src[t] + feat[tab_d(t)][dst] . v_dst[t] + c[t]
//
// vs round 5:
//  * All per-type constants (folded vectors, table base pointers, bias) live
//    in shared-memory LUTs indexed by edge type -> no flag math, no 16 regs
//    of folded vectors, target <=40 regs for >=75% occupancy.
//  * 2 edges per thread (int2/float2 streams) halves live gather state;
//    total memory-level parallelism unchanged (2x threads).
//  * Keeps __ldcs/__stcs on streams (DRAM% win from round 5).
// ---------------------------------------------------------------------------

__device__ __forceinline__ float dot4(float4 a, float4 b) {
    return a.x * b.x + a.y * b.y + a.z * b.z + a.w * b.w;
}

__global__ void __launch_bounds__(256, 6) fused_k(
    const float4* __restrict__ ax, const float4* __restrict__ px,
    const int* __restrict__ src, const int* __restrict__ dst,
    const int* __restrict__ typ, float* __restrict__ out, int E,
    const float* __restrict__ Wa, const float* __restrict__ ba,
    const float* __restrict__ Wp, const float* __restrict__ bp,
    const float* __restrict__ Ws, const float* __restrict__ bs,
    const int* __restrict__ fsrc, const int* __restrict__ fdst)
{
    __shared__ float4 s_vs[4];            // per-type src vector (flag pre-applied)
    __shared__ float4 s_vd[4];            // per-type dst vector
    __shared__ const float4* s_ps[4];     // per-type src table base
    __shared__ const float4* s_pd[4];     // per-type dst table base
    __shared__ float  s_c[4];             // per-type constant

    if (threadIdx.x == 0) {
        float vas[4], vps[4], vad[4], vpd[4];
#pragma unroll
        for (int j = 0; j < 4; j++) {
            float a = 0.f, p = 0.f, ad = 0.f, pd = 0.f;
#pragma unroll
            for (int i = 0; i < 4; i++) {
                float wsi = Ws[i], wsd = Ws[4 + i];
                float wa = Wa[i * 4 + j], wp = Wp[i * 4 + j];
                a  += wsi * wa;  p  += wsi * wp;
                ad += wsd * wa;  pd += wsd * wp;
            }
            vas[j] = a; vps[j] = p; vad[j] = ad; vpd[j] = pd;
        }
        float cas = 0.f, cps = 0.f, cad = 0.f, cpd = 0.f;
#pragma unroll
        for (int i = 0; i < 4; i++) {
            cas += Ws[i]     * ba[i];
            cps += Ws[i]     * bp[i];
            cad += Ws[4 + i] * ba[i];
            cpd += Ws[4 + i] * bp[i];
        }
        float b0 = bs[0];
#pragma unroll
        for (int t = 0; t < 4; t++) {
            int fsv = fsrc[t], fdv = fdst[t];
            s_vs[t]  = fsv ? make_float4(vps[0], vps[1], vps[2], vps[3])
                           : make_float4(vas[0], vas[1], vas[2], vas[3]);
            s_vd[t]  = fdv ? make_float4(vpd[0], vpd[1], vpd[2], vpd[3])
                           : make_float4(vad[0], vad[1], vad[2], vad[3]);
            s_ps[t]  = fsv ? px : ax;
            s_pd[t]  = fdv ? px : ax;
            s_c[t]   = b0 + (fsv ? cps : cas) + (fdv ? cpd : cad);
        }
    }
    __syncthreads();

    int i = blockIdx.x * blockDim.x + threadIdx.x;
    int base = i * 2;
    if (base + 1 < E) {
        int2 s2 = __ldcs(reinterpret_cast<const int2*>(src) + i);
        int2 d2 = __ldcs(reinterpret_cast<const int2*>(dst) + i);
        int2 t2 = __ldcs(reinterpret_cast<const int2*>(typ) + i);

        int t0 = t2.x, t1 = t2.y;
        // All 4 gathers issued before any consumption (max MLP per thread).
        float4 sf0 = __ldg(s_ps[t0] + s2.x);
        float4 df0 = __ldg(s_pd[t0] + d2.x);
        float4 sf1 = __ldg(s_ps[t1] + s2.y);
        float4 df1 = __ldg(s_pd[t1] + d2.y);

        float2 o;
        o.x = dot4(sf0, s_vs[t0]) + dot4(df0, s_vd[t0]) + s_c[t0];
        o.y = dot4(sf1, s_vs[t1]) + dot4(df1, s_vd[t1]) + s_c[t1];
        __stcs(reinterpret_cast<float2*>(out) + i, o);
    } else if (base < E) {
        for (int e = base; e < E; e++) {
            int t = typ[e];
            out[e] = dot4(__ldg(s_ps[t] + src[e]), s_vs[t])
                   + dot4(__ldg(s_pd[t] + dst[e]), s_vd[t]) + s_c[t];
        }
    }
}

extern "C" void kernel_launch(void* const* d_in, const int* in_sizes, int n_in,
                              void* d_out, int out_size)
{
    const float* author_x = (const float*)d_in[0];
    const float* paper_x  = (const float*)d_in[1];
    const int*   src      = (const int*)  d_in[2];
    const int*   dst      = (const int*)  d_in[3];
    const int*   typ      = (const int*)  d_in[4];
    const int*   fsrc     = (const int*)  d_in[5];
    const int*   fdst     = (const int*)  d_in[6];
    const float* Wa       = (const float*)d_in[7];
    const float* ba       = (const float*)d_in[8];
    const float* Wp       = (const float*)d_in[9];
    const float* bp       = (const float*)d_in[10];
    const float* Ws       = (const float*)d_in[11];
    const float* bs       = (const float*)d_in[12];

    int E = in_sizes[2];
    int pairs = (E + 1) / 2;
    int eb = (pairs + 255) / 256;
    fused_k<<<eb, 256>>>((const float4*)author_x, (const float4*)paper_x,
                         src, dst, typ, (float*)d_out, E,
                         Wa, ba, Wp, bp, Ws, bs, fsrc, fdst);
}

// round 9
// speedup vs baseline: 1.0369x; 1.0369x over previous
#include <cuda_runtime.h>

// ---------------------------------------------------------------------------
// TinyMixedHeteroLinkPredictor — round 9 (= round 8 resubmit; two consecutive
// infra container failures, source never actually benched):
// fused, 4 edges/thread, smem LUT, pairwise gathers.
//
//   logit(e) = feat[tab_s(t)][src] . v_src[t] + feat[tab_d(t)][dst] . v_dst[t] + c[t]
//
// Lessons encoded:
//  * 16B/lane streams (int4) — 8B streams double stream wavefronts (round 6).
//  * smem LUT for per-type constants — saves ~16 regs (round 6: 48 -> 40).
//  * pairwise gather consumption — caps live gather regs at 16; with the LUT
//    this targets <=40 regs -> 6 blocks/SM (__launch_bounds__(256, 6)).
//  * __ldcs/__stcs on streams keeps the 64 MB tables L2-resident (round 5:
//    DRAM 51% -> 36%). Gathers via __ldg (plain .nc) — no inline PTX.
// ---------------------------------------------------------------------------

__device__ __forceinline__ float dot4(float4 a, float4 b) {
    return a.x * b.x + a.y * b.y + a.z * b.z + a.w * b.w;
}

__global__ void __launch_bounds__(256, 6) fused_k(
    const float4* __restrict__ ax, const float4* __restrict__ px,
    const int* __restrict__ src, const int* __restrict__ dst,
    const int* __restrict__ typ, float* __restrict__ out, int E,
    const float* __restrict__ Wa, const float* __restrict__ ba,
    const float* __restrict__ Wp, const float* __restrict__ bp,
    const float* __restrict__ Ws, const float* __restrict__ bs,
    const int* __restrict__ fsrc, const int* __restrict__ fdst)
{
    __shared__ float4 s_vs[4];          // per-type src vector (flag pre-applied)
    __shared__ float4 s_vd[4];          // per-type dst vector
    __shared__ const float4* s_ps[4];   // per-type src table base
    __shared__ const float4* s_pd[4];   // per-type dst table base
    __shared__ float  s_c[4];           // per-type constant

    if (threadIdx.x == 0) {
        float vas[4], vps[4], vad[4], vpd[4];
#pragma unroll
        for (int j = 0; j < 4; j++) {
            float a = 0.f, p = 0.f, ad = 0.f, pd = 0.f;
#pragma unroll
            for (int i = 0; i < 4; i++) {
                float wsi = Ws[i], wsd = Ws[4 + i];
                float wa = Wa[i * 4 + j], wp = Wp[i * 4 + j];
                a  += wsi * wa;  p  += wsi * wp;
                ad += wsd * wa;  pd += wsd * wp;
            }
            vas[j] = a; vps[j] = p; vad[j] = ad; vpd[j] = pd;
        }
        float cas = 0.f, cps = 0.f, cad = 0.f, cpd = 0.f;
#pragma unroll
        for (int i = 0; i < 4; i++) {
            cas += Ws[i]     * ba[i];
            cps += Ws[i]     * bp[i];
            cad += Ws[4 + i] * ba[i];
            cpd += Ws[4 + i] * bp[i];
        }
        float b0 = bs[0];
#pragma unroll
        for (int t = 0; t < 4; t++) {
            int fsv = fsrc[t], fdv = fdst[t];
            s_vs[t] = fsv ? make_float4(vps[0], vps[1], vps[2], vps[3])
                          : make_float4(vas[0], vas[1], vas[2], vas[3]);
            s_vd[t] = fdv ? make_float4(vpd[0], vpd[1], vpd[2], vpd[3])
                          : make_float4(vad[0], vad[1], vad[2], vad[3]);
            s_ps[t] = fsv ? px : ax;
            s_pd[t] = fdv ? px : ax;
            s_c[t]  = b0 + (fsv ? cps : cas) + (fdv ? cpd : cad);
        }
    }
    __syncthreads();

    int i = blockIdx.x * blockDim.x + threadIdx.x;
    int base = i * 4;
    if (base + 3 < E) {
        int4 s4 = __ldcs(reinterpret_cast<const int4*>(src) + i);
        int4 d4 = __ldcs(reinterpret_cast<const int4*>(dst) + i);
        int4 t4 = __ldcs(reinterpret_cast<const int4*>(typ) + i);

        int se[4] = {s4.x, s4.y, s4.z, s4.w};
        int de[4] = {d4.x, d4.y, d4.z, d4.w};
        int te[4] = {t4.x, t4.y, t4.z, t4.w};

        float r[4];
#pragma unroll
        for (int pair = 0; pair < 2; pair++) {
            int k0 = pair * 2 + 0, k1 = pair * 2 + 1;
            int t0 = te[k0], t1 = te[k1];
            // 4 gathers in flight per pair; <=16 regs of gather data live.
            float4 sf0 = __ldg(s_ps[t0] + se[k0]);
            float4 df0 = __ldg(s_pd[t0] + de[k0]);
            float4 sf1 = __ldg(s_ps[t1] + se[k1]);
            float4 df1 = __ldg(s_pd[t1] + de[k1]);
            r[k0] = dot4(sf0, s_vs[t0]) + dot4(df0, s_vd[t0]) + s_c[t0];
            r[k1] = dot4(sf1, s_vs[t1]) + dot4(df1, s_vd[t1]) + s_c[t1];
        }

        __stcs(reinterpret_cast<float4*>(out) + i,
               make_float4(r[0], r[1], r[2], r[3]));
    } else if (base < E) {
        for (int e = base; e < E; e++) {
            int t = typ[e];
            out[e] = dot4(__ldg(s_ps[t] + src[e]), s_vs[t])
                   + dot4(__ldg(s_pd[t] + dst[e]), s_vd[t]) + s_c[t];
        }
    }
}

extern "C" void kernel_launch(void* const* d_in, const int* in_sizes, int n_in,
                              void* d_out, int out_size)
{
    const float* author_x = (const float*)d_in[0];
    const float* paper_x  = (const float*)d_in[1];
    const int*   src      = (const int*)  d_in[2];
    const int*   dst      = (const int*)  d_in[3];
    const int*   typ      = (const int*)  d_in[4];
    const int*   fsrc     = (const int*)  d_in[5];
    const int*   fdst     = (const int*)  d_in[6];
    const float* Wa       = (const float*)d_in[7];
    const float* ba       = (const float*)d_in[8];
    const float* Wp       = (const float*)d_in[9];
    const float* bp       = (const float*)d_in[10];
    const float* Ws       = (const float*)d_in[11];
    const float* bs       = (const float*)d_in[12];

    int E = in_sizes[2];
    int quads = (E + 3) / 4;
    int eb = (quads + 255) / 256;
    fused_k<<<eb, 256>>>((const float4*)author_x, (const float4*)paper_x,
                         src, dst, typ, (float*)d_out, E,
                         Wa, ba, Wp, bp, Ws, bs, fsrc, fdst);
}